// round 14
// baseline (speedup 1.0000x reference)
#include <cuda_runtime.h>
#include <math.h>

#define MODEL_DIM 128
#define N_FRAMES 128
#define N_SAMPLES 32768
#define N_TABLES 16
#define TABLE_SIZE 512
#define BATCH 8
#define INV_STD 100.0f
#define GAUSS_SCALE 39.894228040143274f   // 1/(0.01*sqrt(2*pi))

// ------------------- scratch (static device globals; no runtime alloc) ---------
__device__ float g_table[BATCH][TABLE_SIZE];   // normalized selected table
__device__ float g_values[BATCH];
__device__ float g_freqf[BATCH][N_FRAMES];     // (freq mlp out)^2 per frame
__device__ float g_envf[BATCH][N_FRAMES];      // (env mlp out)^2 per frame
__device__ float g_C[BATCH][N_FRAMES];         // fp32 cumsum prefix per segment

__device__ __forceinline__ float ex2_ftz(float a) {
    float r;
    asm("ex2.approx.ftz.f32 %0, %1;" : "=f"(r) : "f"(a));
    return r;
}

// ---------------------------------------------------------------------------
// prep_kernel: 9 blocks x 1024 threads, NO cross-block dependencies.
//   block 0   : tc head for all 8 rows -> argmax/max -> normalize selected tables
//   block 1+b : env & freq MLPs for batch row b; frame outputs + fp32 prefix scan.
// Ends with griddepcontrol.launch_dependents (PDL primary).
// ---------------------------------------------------------------------------
__global__ void prep_kernel(const float* __restrict__ x,
                            const float* __restrict__ wavetables,
                            const float* __restrict__ tc_w1, const float* __restrict__ tc_b1,
                            const float* __restrict__ tc_w2, const float* __restrict__ tc_b2,
                            const float* __restrict__ tc_w3, const float* __restrict__ tc_b3,
                            const float* __restrict__ env_w1, const float* __restrict__ env_b1,
                            const float* __restrict__ env_w2, const float* __restrict__ env_b2,
                            const float* __restrict__ env_w3, const float* __restrict__ env_b3,
                            const float* __restrict__ fr_w1, const float* __restrict__ fr_b1,
                            const float* __restrict__ fr_w2, const float* __restrict__ fr_b2,
                            const float* __restrict__ fr_w3, const float* __restrict__ fr_b3)
{
    const int tid = threadIdx.x;

    if (blockIdx.x == 0) {
        // ---------------- tc head, all 8 batch rows ----------------
        __shared__ float hs[BATCH * MODEL_DIM];
        __shared__ float h2[BATCH * MODEL_DIM];
        __shared__ float out_s[BATCH * 256];
        __shared__ float s_scores[BATCH * N_TABLES];
        __shared__ int   s_idx[BATCH];

        hs[tid] = x[tid];
        __syncthreads();

        {   // layer1
            int b = tid >> 7, o = tid & 127;
            float acc = tc_b1[o];
            const float* hb = &hs[b * MODEL_DIM];
            #pragma unroll 8
            for (int i = 0; i < MODEL_DIM; i++)
                acc = fmaf(hb[i], tc_w1[i * MODEL_DIM + o], acc);
            h2[tid] = (acc >= 0.0f) ? acc : 0.2f * acc;
        }
        __syncthreads();
        {   // layer2
            int b = tid >> 7, o = tid & 127;
            float acc = tc_b2[o];
            const float* hb = &h2[b * MODEL_DIM];
            #pragma unroll 8
            for (int i = 0; i < MODEL_DIM; i++)
                acc = fmaf(hb[i], tc_w2[i * MODEL_DIM + o], acc);
            hs[tid] = (acc >= 0.0f) ? acc : 0.2f * acc;
        }
        __syncthreads();
        // layer3: outdim 256 -> 2048 outputs, 2 per thread
        #pragma unroll
        for (int r = 0; r < 2; r++) {
            int oo = tid + r * 1024;
            int b = oo >> 8, o = oo & 255;
            float acc = tc_b3[o];
            const float* hb = &hs[b * MODEL_DIM];
            #pragma unroll 8
            for (int i = 0; i < MODEL_DIM; i++)
                acc = fmaf(hb[i], tc_w3[i * 256 + o], acc);
            out_s[oo] = acc;
        }
        __syncthreads();

        if (tid < BATCH * N_TABLES) {
            int b = tid >> 4, n = tid & 15;
            float s = 0.0f;
            #pragma unroll
            for (int k = 0; k < 16; k++) s += out_s[b * 256 + n * 16 + k];
            s_scores[tid] = s * (1.0f / 16.0f);
        }
        __syncthreads();
        if (tid < BATCH) {
            float best = s_scores[tid * N_TABLES];
            int bi = 0;
            #pragma unroll
            for (int n = 1; n < N_TABLES; n++) {
                float v = s_scores[tid * N_TABLES + n];
                if (v > best) { best = v; bi = n; }   // first-max ties == argmax
            }
            g_values[tid] = best;
            s_idx[tid] = bi;
        }
        __syncthreads();

        // ------------- normalize selected tables: warp w handles batch w -------------
        const int wid = tid >> 5, lane = tid & 31;
        if (wid < BATCH) {
            const float* row = wavetables + s_idx[wid] * TABLE_SIZE;
            float m = -3.4e38f;
            #pragma unroll
            for (int i = 0; i < 16; i++)
                m = fmaxf(m, __ldg(&row[lane + i * 32]));
            #pragma unroll
            for (int off = 16; off > 0; off >>= 1)
                m = fmaxf(m, __shfl_xor_sync(0xFFFFFFFFu, m, off));
            float denom = m + 1e-8f;
            #pragma unroll
            for (int i = 0; i < 16; i++) {
                int j = lane + i * 32;
                g_table[wid][j] = __ldg(&row[j]) / denom;
            }
        }
        __syncthreads();
        asm volatile("griddepcontrol.launch_dependents;" ::: "memory");
        return;
    }

    // ---------------- blocks 1..8: per-batch env/freq MLP + frame outputs ----------
    const int b = blockIdx.x - 1;

    __shared__ float s_x[MODEL_DIM];
    __shared__ float s_part[8 * MODEL_DIM];
    __shared__ float s_h[MODEL_DIM];
    __shared__ float s_env[N_FRAMES];
    __shared__ float s_freq[N_FRAMES];
    __shared__ float s_C[N_FRAMES];

    if (tid < MODEL_DIM) s_x[tid] = x[b * MODEL_DIM + tid];
    __syncthreads();

    const int r = tid >> 7;        // 0..7 : k-slice
    const int o = tid & 127;       // output index

    #define MLP3(W1, B1, W2, B2, W3, B3, DST)                                   \
    {                                                                            \
        float p = 0.0f;                                                          \
        {                                                                        \
            const int k0 = r * 16;                                               \
            _Pragma("unroll")                                                    \
            for (int k = 0; k < 16; k++)                                         \
                p = fmaf(s_x[k0 + k], W1[(k0 + k) * MODEL_DIM + o], p);          \
            s_part[r * MODEL_DIM + o] = p;                                       \
        }                                                                        \
        __syncthreads();                                                         \
        if (tid < MODEL_DIM) {                                                   \
            float acc = B1[tid];                                                 \
            _Pragma("unroll")                                                    \
            for (int rr = 0; rr < 8; rr++) acc += s_part[rr * MODEL_DIM + tid];  \
            s_h[tid] = (acc >= 0.0f) ? acc : 0.2f * acc;                         \
        }                                                                        \
        __syncthreads();                                                         \
        p = 0.0f;                                                                \
        {                                                                        \
            const int k0 = r * 16;                                               \
            _Pragma("unroll")                                                    \
            for (int k = 0; k < 16; k++)                                         \
                p = fmaf(s_h[k0 + k], W2[(k0 + k) * MODEL_DIM + o], p);          \
            s_part[r * MODEL_DIM + o] = p;                                       \
        }                                                                        \
        __syncthreads();                                                         \
        if (tid < MODEL_DIM) {                                                   \
            float acc = B2[tid];                                                 \
            _Pragma("unroll")                                                    \
            for (int rr = 0; rr < 8; rr++) acc += s_part[rr * MODEL_DIM + tid];  \
            s_part[tid] = (acc >= 0.0f) ? acc : 0.2f * acc;  /* reuse row 0 */   \
        }                                                                        \
        __syncthreads();                                                         \
        if (tid < MODEL_DIM) s_h[tid] = s_part[tid];                             \
        __syncthreads();                                                         \
        p = 0.0f;                                                                \
        {                                                                        \
            const int k0 = r * 16;                                               \
            _Pragma("unroll")                                                    \
            for (int k = 0; k < 16; k++)                                         \
                p = fmaf(s_h[k0 + k], W3[(k0 + k) * N_FRAMES + o], p);           \
            s_part[r * MODEL_DIM + o] = p;                                       \
        }                                                                        \
        __syncthreads();                                                         \
        if (tid < N_FRAMES) {                                                    \
            float acc = B3[tid];                                                 \
            _Pragma("unroll")                                                    \
            for (int rr = 0; rr < 8; rr++) acc += s_part[rr * MODEL_DIM + tid];  \
            DST[tid] = acc * acc;  /* squared */                                 \
        }                                                                        \
        __syncthreads();                                                         \
    }

    MLP3(env_w1, env_b1, env_w2, env_b2, env_w3, env_b3, s_env)
    MLP3(fr_w1,  fr_b1,  fr_w2,  fr_b2,  fr_w3,  fr_b3,  s_freq)

    // -------- segment prefix: a[0]=128*f0 (clamp region), a[j]=128*(f_{j-1}+f_j) --------
    if (tid < N_FRAMES) {
        s_C[tid] = (tid == 0) ? 128.0f * s_freq[0]
                              : 128.0f * (s_freq[tid - 1] + s_freq[tid]);
    }
    __syncthreads();
    // Hillis-Steele inclusive scan over 128 floats
    #pragma unroll
    for (int off = 1; off < N_FRAMES; off <<= 1) {
        float v = 0.0f;
        if (tid < N_FRAMES && tid >= off) v = s_C[tid - off];
        __syncthreads();
        if (tid < N_FRAMES && tid >= off) s_C[tid] += v;
        __syncthreads();
    }

    // frame-level outputs only (1.5 KB/batch) — writer reconstructs per-sample
    if (tid < N_FRAMES) {
        g_freqf[b][tid] = s_freq[tid];
        g_envf[b][tid]  = s_env[tid];
        g_C[b][tid]     = s_C[tid];
    }
    __syncthreads();
    asm volatile("griddepcontrol.launch_dependents;" ::: "memory");
}

// ---------------------------------------------------------------------------
// Fused writer (PDL secondary): waits on prep's grid dependency, then
// reconstructs phase/env warp-uniformly (fp32 closed form), writes the
// 512-col Gaussian row, accumulates sampled[b][t].
// ---------------------------------------------------------------------------
__global__ void fused_writer(float* __restrict__ out_kernel,
                             float* __restrict__ out_sampled)
{
    asm volatile("griddepcontrol.wait;" ::: "memory");

    const int wg = (blockIdx.x * blockDim.x + threadIdx.x) >> 5;   // row id
    const int lane = threadIdx.x & 31;
    const int b = wg >> 15;
    const int t = wg & (N_SAMPLES - 1);

    // ---- warp-uniform fp32 closed-form phase + env ----
    float c, envv;
    if (t < 128) {
        const float f0 = __ldg(&g_freqf[b][0]);
        c = (float)(t + 1) * f0;
        envv = __ldg(&g_envf[b][0]);
    } else if (t >= 32640) {
        c = __ldg(&g_C[b][127]) + (float)(t - 32639) * __ldg(&g_freqf[b][127]);
        envv = __ldg(&g_envf[b][127]);
    } else {
        const int k = (t - 128) >> 8;
        const int n = (t - 128) & 255;
        const float A  = __ldg(&g_freqf[b][k]);
        const float Bf = __ldg(&g_freqf[b][k + 1]) - A;
        const float np1 = (float)(n + 1);
        c = __ldg(&g_C[b][k]) + np1 * A + Bf * (np1 * np1 * (1.0f / 512.0f));
        const float w = ((float)n + 0.5f) * (1.0f / 256.0f);
        const float E0 = __ldg(&g_envf[b][k]);
        envv = fmaf(w, __ldg(&g_envf[b][k + 1]) - E0, E0);
    }
    const float phi = fmodf(c, 1.0f);

    const float p100 = phi * INV_STD;
    const int   jc   = __float2int_rn(phi * 511.0f);
    const int   clo  = jc - 70;
    const int   chi  = jc + 70;

    const float C2 = -0.7213475204444817f;   // -0.5 * log2(e)
    const float KB =  5.3180608409839085f;   // log2(GAUSS_SCALE)

    float4* rowp = reinterpret_cast<float4*>(out_kernel) + ((long long)wg << 7);
    const float4* tab4 = reinterpret_cast<const float4*>(g_table[b]);
    float acc = 0.0f;

    #pragma unroll
    for (int i = 0; i < 4; i++) {
        const int cblk = i * 128;
        if (chi < cblk || clo > cblk + 127) {
            float4 z4 = make_float4(0.0f, 0.0f, 0.0f, 0.0f);
            __stcs(&rowp[i * 32 + lane], z4);
        } else {
            const int col0 = (i * 32 + lane) * 4;
            const float4 tv = __ldg(&tab4[i * 32 + lane]);
            const float* tp = &tv.x;
            float4 v;
            float* vp = &v.x;
            #pragma unroll
            for (int k = 0; k < 4; k++) {
                float z = fmaf((float)(col0 + k), INV_STD / 511.0f, -p100);
                float e = ex2_ftz(fmaf(z * z, C2, KB));   // GAUSS_SCALE folded in
                vp[k] = e;
                acc = fmaf(tp[k], e, acc);
            }
            __stcs(&rowp[i * 32 + lane], v);
        }
    }

    #pragma unroll
    for (int off = 16; off > 0; off >>= 1)
        acc += __shfl_down_sync(0xFFFFFFFFu, acc, off);

    if (lane == 0)
        out_sampled[wg] = acc * envv * g_values[b];   // scale already in acc
}

// ---------------------------------------------------------------------------
extern "C" void kernel_launch(void* const* d_in, const int* in_sizes, int n_in,
                              void* d_out, int out_size)
{
    const float* x          = (const float*)d_in[0];
    const float* wavetables = (const float*)d_in[1];
    const float* tc_w1 = (const float*)d_in[2];  const float* tc_b1 = (const float*)d_in[3];
    const float* tc_w2 = (const float*)d_in[4];  const float* tc_b2 = (const float*)d_in[5];
    const float* tc_w3 = (const float*)d_in[6];  const float* tc_b3 = (const float*)d_in[7];
    const float* env_w1 = (const float*)d_in[8];  const float* env_b1 = (const float*)d_in[9];
    const float* env_w2 = (const float*)d_in[10]; const float* env_b2 = (const float*)d_in[11];
    const float* env_w3 = (const float*)d_in[12]; const float* env_b3 = (const float*)d_in[13];
    const float* fr_w1 = (const float*)d_in[14]; const float* fr_b1 = (const float*)d_in[15];
    const float* fr_w2 = (const float*)d_in[16]; const float* fr_b2 = (const float*)d_in[17];
    const float* fr_w3 = (const float*)d_in[18]; const float* fr_b3 = (const float*)d_in[19];

    float* out = (float*)d_out;
    float* out_sampled = out;                        // (8, 1, 32768)
    float* out_kernel  = out + BATCH * N_SAMPLES;    // (8, 32768, 512)

    prep_kernel<<<9, 1024>>>(x, wavetables,
        tc_w1, tc_b1, tc_w2, tc_b2, tc_w3, tc_b3,
        env_w1, env_b1, env_w2, env_b2, env_w3, env_b3,
        fr_w1, fr_b1, fr_w2, fr_b2, fr_w3, fr_b3);

    // PDL: writer launches while prep drains; griddepcontrol.wait inside
    // guarantees prep's global stores are visible before use.
    cudaLaunchConfig_t cfg = {};
    cfg.gridDim  = dim3((BATCH * N_SAMPLES) / 8, 1, 1);   // 32768 blocks
    cfg.blockDim = dim3(256, 1, 1);
    cfg.dynamicSmemBytes = 0;
    cfg.stream = 0;
    cudaLaunchAttribute attrs[1];
    attrs[0].id = cudaLaunchAttributeProgrammaticStreamSerialization;
    attrs[0].val.programmaticStreamSerializationAllowed = 1;
    cfg.attrs = attrs;
    cfg.numAttrs = 1;
    cudaLaunchKernelEx(&cfg, fused_writer, out_kernel, out_sampled);
}

// round 15
// speedup vs baseline: 1.0049x; 1.0049x over previous
#include <cuda_runtime.h>
#include <math.h>

#define MODEL_DIM 128
#define N_FRAMES 128
#define N_SAMPLES 32768
#define N_TABLES 16
#define TABLE_SIZE 512
#define BATCH 8
#define INV_STD 100.0f
#define GAUSS_SCALE 39.894228040143274f   // 1/(0.01*sqrt(2*pi))

// ------------------- scratch (static device globals; no runtime alloc) ---------
__device__ float g_table[BATCH][TABLE_SIZE];   // normalized selected table
__device__ float g_values[BATCH];
__device__ float g_freqf[BATCH][N_FRAMES];     // (freq mlp out)^2 per frame
__device__ float g_envf[BATCH][N_FRAMES];      // (env mlp out)^2 per frame
__device__ float g_C[BATCH][N_FRAMES];         // fp32 cumsum prefix per segment

__device__ __forceinline__ float ex2_ftz(float a) {
    float r;
    asm("ex2.approx.ftz.f32 %0, %1;" : "=f"(r) : "f"(a));
    return r;
}

// ---------------------------------------------------------------------------
// prep_kernel: 9 blocks x 1024 threads, NO cross-block dependencies.
//   block 0   : tc head for all 8 rows -> argmax/max -> normalize selected tables
//   block 1+b : env & freq MLPs for batch row b; frame outputs + fp32 prefix scan.
// Ends with griddepcontrol.launch_dependents (PDL primary).
// ---------------------------------------------------------------------------
__global__ void prep_kernel(const float* __restrict__ x,
                            const float* __restrict__ wavetables,
                            const float* __restrict__ tc_w1, const float* __restrict__ tc_b1,
                            const float* __restrict__ tc_w2, const float* __restrict__ tc_b2,
                            const float* __restrict__ tc_w3, const float* __restrict__ tc_b3,
                            const float* __restrict__ env_w1, const float* __restrict__ env_b1,
                            const float* __restrict__ env_w2, const float* __restrict__ env_b2,
                            const float* __restrict__ env_w3, const float* __restrict__ env_b3,
                            const float* __restrict__ fr_w1, const float* __restrict__ fr_b1,
                            const float* __restrict__ fr_w2, const float* __restrict__ fr_b2,
                            const float* __restrict__ fr_w3, const float* __restrict__ fr_b3)
{
    const int tid = threadIdx.x;

    if (blockIdx.x == 0) {
        // ---------------- tc head, all 8 batch rows ----------------
        __shared__ float hs[BATCH * MODEL_DIM];
        __shared__ float h2[BATCH * MODEL_DIM];
        __shared__ float out_s[BATCH * 256];
        __shared__ float s_scores[BATCH * N_TABLES];
        __shared__ int   s_idx[BATCH];

        hs[tid] = x[tid];
        __syncthreads();

        {   // layer1
            int b = tid >> 7, o = tid & 127;
            float acc = tc_b1[o];
            const float* hb = &hs[b * MODEL_DIM];
            #pragma unroll 8
            for (int i = 0; i < MODEL_DIM; i++)
                acc = fmaf(hb[i], tc_w1[i * MODEL_DIM + o], acc);
            h2[tid] = (acc >= 0.0f) ? acc : 0.2f * acc;
        }
        __syncthreads();
        {   // layer2
            int b = tid >> 7, o = tid & 127;
            float acc = tc_b2[o];
            const float* hb = &h2[b * MODEL_DIM];
            #pragma unroll 8
            for (int i = 0; i < MODEL_DIM; i++)
                acc = fmaf(hb[i], tc_w2[i * MODEL_DIM + o], acc);
            hs[tid] = (acc >= 0.0f) ? acc : 0.2f * acc;
        }
        __syncthreads();
        // layer3: outdim 256 -> 2048 outputs, 2 per thread
        #pragma unroll
        for (int r = 0; r < 2; r++) {
            int oo = tid + r * 1024;
            int b = oo >> 8, o = oo & 255;
            float acc = tc_b3[o];
            const float* hb = &hs[b * MODEL_DIM];
            #pragma unroll 8
            for (int i = 0; i < MODEL_DIM; i++)
                acc = fmaf(hb[i], tc_w3[i * 256 + o], acc);
            out_s[oo] = acc;
        }
        __syncthreads();

        if (tid < BATCH * N_TABLES) {
            int b = tid >> 4, n = tid & 15;
            float s = 0.0f;
            #pragma unroll
            for (int k = 0; k < 16; k++) s += out_s[b * 256 + n * 16 + k];
            s_scores[tid] = s * (1.0f / 16.0f);
        }
        __syncthreads();
        if (tid < BATCH) {
            float best = s_scores[tid * N_TABLES];
            int bi = 0;
            #pragma unroll
            for (int n = 1; n < N_TABLES; n++) {
                float v = s_scores[tid * N_TABLES + n];
                if (v > best) { best = v; bi = n; }   // first-max ties == argmax
            }
            g_values[tid] = best;
            s_idx[tid] = bi;
        }
        __syncthreads();

        // ------------- normalize selected tables: warp w handles batch w -------------
        const int wid = tid >> 5, lane = tid & 31;
        if (wid < BATCH) {
            const float* row = wavetables + s_idx[wid] * TABLE_SIZE;
            float m = -3.4e38f;
            #pragma unroll
            for (int i = 0; i < 16; i++)
                m = fmaxf(m, __ldg(&row[lane + i * 32]));
            #pragma unroll
            for (int off = 16; off > 0; off >>= 1)
                m = fmaxf(m, __shfl_xor_sync(0xFFFFFFFFu, m, off));
            float denom = m + 1e-8f;
            #pragma unroll
            for (int i = 0; i < 16; i++) {
                int j = lane + i * 32;
                g_table[wid][j] = __ldg(&row[j]) / denom;
            }
        }
        __syncthreads();
        asm volatile("griddepcontrol.launch_dependents;" ::: "memory");
        return;
    }

    // ---------------- blocks 1..8: per-batch env/freq MLP + frame outputs ----------
    const int b = blockIdx.x - 1;

    __shared__ float s_x[MODEL_DIM];
    __shared__ float s_part[8 * MODEL_DIM];
    __shared__ float s_h[MODEL_DIM];
    __shared__ float s_env[N_FRAMES];
    __shared__ float s_freq[N_FRAMES];
    __shared__ float s_C[N_FRAMES];

    if (tid < MODEL_DIM) s_x[tid] = x[b * MODEL_DIM + tid];
    __syncthreads();

    const int r = tid >> 7;        // 0..7 : k-slice
    const int o = tid & 127;       // output index

    #define MLP3(W1, B1, W2, B2, W3, B3, DST)                                   \
    {                                                                            \
        float p = 0.0f;                                                          \
        {                                                                        \
            const int k0 = r * 16;                                               \
            _Pragma("unroll")                                                    \
            for (int k = 0; k < 16; k++)                                         \
                p = fmaf(s_x[k0 + k], W1[(k0 + k) * MODEL_DIM + o], p);          \
            s_part[r * MODEL_DIM + o] = p;                                       \
        }                                                                        \
        __syncthreads();                                                         \
        if (tid < MODEL_DIM) {                                                   \
            float acc = B1[tid];                                                 \
            _Pragma("unroll")                                                    \
            for (int rr = 0; rr < 8; rr++) acc += s_part[rr * MODEL_DIM + tid];  \
            s_h[tid] = (acc >= 0.0f) ? acc : 0.2f * acc;                         \
        }                                                                        \
        __syncthreads();                                                         \
        p = 0.0f;                                                                \
        {                                                                        \
            const int k0 = r * 16;                                               \
            _Pragma("unroll")                                                    \
            for (int k = 0; k < 16; k++)                                         \
                p = fmaf(s_h[k0 + k], W2[(k0 + k) * MODEL_DIM + o], p);          \
            s_part[r * MODEL_DIM + o] = p;                                       \
        }                                                                        \
        __syncthreads();                                                         \
        if (tid < MODEL_DIM) {                                                   \
            float acc = B2[tid];                                                 \
            _Pragma("unroll")                                                    \
            for (int rr = 0; rr < 8; rr++) acc += s_part[rr * MODEL_DIM + tid];  \
            s_part[tid] = (acc >= 0.0f) ? acc : 0.2f * acc;  /* reuse row 0 */   \
        }                                                                        \
        __syncthreads();                                                         \
        if (tid < MODEL_DIM) s_h[tid] = s_part[tid];                             \
        __syncthreads();                                                         \
        p = 0.0f;                                                                \
        {                                                                        \
            const int k0 = r * 16;                                               \
            _Pragma("unroll")                                                    \
            for (int k = 0; k < 16; k++)                                         \
                p = fmaf(s_h[k0 + k], W3[(k0 + k) * N_FRAMES + o], p);           \
            s_part[r * MODEL_DIM + o] = p;                                       \
        }                                                                        \
        __syncthreads();                                                         \
        if (tid < N_FRAMES) {                                                    \
            float acc = B3[tid];                                                 \
            _Pragma("unroll")                                                    \
            for (int rr = 0; rr < 8; rr++) acc += s_part[rr * MODEL_DIM + tid];  \
            DST[tid] = acc * acc;  /* squared */                                 \
        }                                                                        \
        __syncthreads();                                                         \
    }

    MLP3(env_w1, env_b1, env_w2, env_b2, env_w3, env_b3, s_env)
    MLP3(fr_w1,  fr_b1,  fr_w2,  fr_b2,  fr_w3,  fr_b3,  s_freq)

    // -------- segment prefix: a[0]=128*f0 (clamp region), a[j]=128*(f_{j-1}+f_j) --------
    if (tid < N_FRAMES) {
        s_C[tid] = (tid == 0) ? 128.0f * s_freq[0]
                              : 128.0f * (s_freq[tid - 1] + s_freq[tid]);
    }
    __syncthreads();
    // Hillis-Steele inclusive scan over 128 floats
    #pragma unroll
    for (int off = 1; off < N_FRAMES; off <<= 1) {
        float v = 0.0f;
        if (tid < N_FRAMES && tid >= off) v = s_C[tid - off];
        __syncthreads();
        if (tid < N_FRAMES && tid >= off) s_C[tid] += v;
        __syncthreads();
    }

    // frame-level outputs only (1.5 KB/batch) — writer reconstructs per-sample
    if (tid < N_FRAMES) {
        g_freqf[b][tid] = s_freq[tid];
        g_envf[b][tid]  = s_env[tid];
        g_C[b][tid]     = s_C[tid];
    }
    __syncthreads();
    asm volatile("griddepcontrol.launch_dependents;" ::: "memory");
}

// ---------------------------------------------------------------------------
// Fused writer (PDL secondary): waits on prep's grid dependency, then
// reconstructs phase/env warp-uniformly (fp32 closed form), writes the
// 512-col Gaussian row, accumulates sampled[b][t].
// ---------------------------------------------------------------------------
__global__ void fused_writer(float* __restrict__ out_kernel,
                             float* __restrict__ out_sampled)
{
    asm volatile("griddepcontrol.wait;" ::: "memory");

    const int wg = (blockIdx.x * blockDim.x + threadIdx.x) >> 5;   // row id
    const int lane = threadIdx.x & 31;
    const int b = wg >> 15;
    const int t = wg & (N_SAMPLES - 1);

    // ---- warp-uniform fp32 closed-form phase + env ----
    float c, envv;
    if (t < 128) {
        const float f0 = __ldg(&g_freqf[b][0]);
        c = (float)(t + 1) * f0;
        envv = __ldg(&g_envf[b][0]);
    } else if (t >= 32640) {
        c = __ldg(&g_C[b][127]) + (float)(t - 32639) * __ldg(&g_freqf[b][127]);
        envv = __ldg(&g_envf[b][127]);
    } else {
        const int k = (t - 128) >> 8;
        const int n = (t - 128) & 255;
        const float A  = __ldg(&g_freqf[b][k]);
        const float Bf = __ldg(&g_freqf[b][k + 1]) - A;
        const float np1 = (float)(n + 1);
        c = __ldg(&g_C[b][k]) + np1 * A + Bf * (np1 * np1 * (1.0f / 512.0f));
        const float w = ((float)n + 0.5f) * (1.0f / 256.0f);
        const float E0 = __ldg(&g_envf[b][k]);
        envv = fmaf(w, __ldg(&g_envf[b][k + 1]) - E0, E0);
    }
    const float phi = fmodf(c, 1.0f);

    const float p100 = phi * INV_STD;
    const int   jc   = __float2int_rn(phi * 511.0f);
    const int   clo  = jc - 70;
    const int   chi  = jc + 70;

    const float C2 = -0.7213475204444817f;   // -0.5 * log2(e)
    const float KB =  5.3180608409839085f;   // log2(GAUSS_SCALE)

    float4* rowp = reinterpret_cast<float4*>(out_kernel) + ((long long)wg << 7);
    const float4* tab4 = reinterpret_cast<const float4*>(g_table[b]);
    float acc = 0.0f;

    #pragma unroll
    for (int i = 0; i < 4; i++) {
        const int cblk = i * 128;
        if (chi < cblk || clo > cblk + 127) {
            float4 z4 = make_float4(0.0f, 0.0f, 0.0f, 0.0f);
            __stcs(&rowp[i * 32 + lane], z4);
        } else {
            const int col0 = (i * 32 + lane) * 4;
            const float4 tv = __ldg(&tab4[i * 32 + lane]);
            const float* tp = &tv.x;
            float4 v;
            float* vp = &v.x;
            #pragma unroll
            for (int k = 0; k < 4; k++) {
                float z = fmaf((float)(col0 + k), INV_STD / 511.0f, -p100);
                float e = ex2_ftz(fmaf(z * z, C2, KB));   // GAUSS_SCALE folded in
                vp[k] = e;
                acc = fmaf(tp[k], e, acc);
            }
            __stcs(&rowp[i * 32 + lane], v);
        }
    }

    #pragma unroll
    for (int off = 16; off > 0; off >>= 1)
        acc += __shfl_down_sync(0xFFFFFFFFu, acc, off);

    if (lane == 0)
        out_sampled[wg] = acc * envv * g_values[b];   // scale already in acc
}

// ---------------------------------------------------------------------------
extern "C" void kernel_launch(void* const* d_in, const int* in_sizes, int n_in,
                              void* d_out, int out_size)
{
    const float* x          = (const float*)d_in[0];
    const float* wavetables = (const float*)d_in[1];
    const float* tc_w1 = (const float*)d_in[2];  const float* tc_b1 = (const float*)d_in[3];
    const float* tc_w2 = (const float*)d_in[4];  const float* tc_b2 = (const float*)d_in[5];
    const float* tc_w3 = (const float*)d_in[6];  const float* tc_b3 = (const float*)d_in[7];
    const float* env_w1 = (const float*)d_in[8];  const float* env_b1 = (const float*)d_in[9];
    const float* env_w2 = (const float*)d_in[10]; const float* env_b2 = (const float*)d_in[11];
    const float* env_w3 = (const float*)d_in[12]; const float* env_b3 = (const float*)d_in[13];
    const float* fr_w1 = (const float*)d_in[14]; const float* fr_b1 = (const float*)d_in[15];
    const float* fr_w2 = (const float*)d_in[16]; const float* fr_b2 = (const float*)d_in[17];
    const float* fr_w3 = (const float*)d_in[18]; const float* fr_b3 = (const float*)d_in[19];

    float* out = (float*)d_out;
    float* out_sampled = out;                        // (8, 1, 32768)
    float* out_kernel  = out + BATCH * N_SAMPLES;    // (8, 32768, 512)

    prep_kernel<<<9, 1024>>>(x, wavetables,
        tc_w1, tc_b1, tc_w2, tc_b2, tc_w3, tc_b3,
        env_w1, env_b1, env_w2, env_b2, env_w3, env_b3,
        fr_w1, fr_b1, fr_w2, fr_b2, fr_w3, fr_b3);

    // PDL: writer launches while prep drains; griddepcontrol.wait inside
    // guarantees prep's global stores are visible before use.
    cudaLaunchConfig_t cfg = {};
    cfg.gridDim  = dim3((BATCH * N_SAMPLES) / 8, 1, 1);   // 32768 blocks
    cfg.blockDim = dim3(256, 1, 1);
    cfg.dynamicSmemBytes = 0;
    cfg.stream = 0;
    cudaLaunchAttribute attrs[1];
    attrs[0].id = cudaLaunchAttributeProgrammaticStreamSerialization;
    attrs[0].val.programmaticStreamSerializationAllowed = 1;
    cfg.attrs = attrs;
    cfg.numAttrs = 1;
    cudaLaunchKernelEx(&cfg, fused_writer, out_kernel, out_sampled);
}

// round 16
// speedup vs baseline: 1.0056x; 1.0007x over previous
#include <cuda_runtime.h>
#include <math.h>

#define MODEL_DIM 128
#define N_FRAMES 128
#define N_SAMPLES 32768
#define N_TABLES 16
#define TABLE_SIZE 512
#define BATCH 8
#define INV_STD 100.0f
#define GAUSS_SCALE 39.894228040143274f   // 1/(0.01*sqrt(2*pi))

// ------------------- scratch (static device globals; no runtime alloc) ---------
__device__ float g_table[BATCH][TABLE_SIZE];   // normalized selected table
__device__ float g_values[BATCH];
__device__ float g_freqf[BATCH][N_FRAMES];     // (freq mlp out)^2 per frame
__device__ float g_envf[BATCH][N_FRAMES];      // (env mlp out)^2 per frame
__device__ float g_C[BATCH][N_FRAMES];         // fp32 cumsum prefix per segment

__device__ __forceinline__ float ex2_ftz(float a) {
    float r;
    asm("ex2.approx.ftz.f32 %0, %1;" : "=f"(r) : "f"(a));
    return r;
}

// ---------------------------------------------------------------------------
// prep_kernel: 9 blocks x 1024 threads, NO cross-block dependencies.
//   block 0   : tc head for all 8 rows -> argmax/max -> normalize selected tables
//   block 1+b : env & freq MLPs for batch row b; frame outputs + fp32 prefix scan.
// Ends with griddepcontrol.launch_dependents (PDL primary).
// ---------------------------------------------------------------------------
__global__ void prep_kernel(const float* __restrict__ x,
                            const float* __restrict__ wavetables,
                            const float* __restrict__ tc_w1, const float* __restrict__ tc_b1,
                            const float* __restrict__ tc_w2, const float* __restrict__ tc_b2,
                            const float* __restrict__ tc_w3, const float* __restrict__ tc_b3,
                            const float* __restrict__ env_w1, const float* __restrict__ env_b1,
                            const float* __restrict__ env_w2, const float* __restrict__ env_b2,
                            const float* __restrict__ env_w3, const float* __restrict__ env_b3,
                            const float* __restrict__ fr_w1, const float* __restrict__ fr_b1,
                            const float* __restrict__ fr_w2, const float* __restrict__ fr_b2,
                            const float* __restrict__ fr_w3, const float* __restrict__ fr_b3)
{
    const int tid = threadIdx.x;

    if (blockIdx.x == 0) {
        // ---------------- tc head, all 8 batch rows ----------------
        __shared__ float hs[BATCH * MODEL_DIM];
        __shared__ float h2[BATCH * MODEL_DIM];
        __shared__ float out_s[BATCH * 256];
        __shared__ float s_scores[BATCH * N_TABLES];
        __shared__ int   s_idx[BATCH];

        hs[tid] = x[tid];
        __syncthreads();

        {   // layer1
            int b = tid >> 7, o = tid & 127;
            float acc = tc_b1[o];
            const float* hb = &hs[b * MODEL_DIM];
            #pragma unroll 8
            for (int i = 0; i < MODEL_DIM; i++)
                acc = fmaf(hb[i], tc_w1[i * MODEL_DIM + o], acc);
            h2[tid] = (acc >= 0.0f) ? acc : 0.2f * acc;
        }
        __syncthreads();
        {   // layer2
            int b = tid >> 7, o = tid & 127;
            float acc = tc_b2[o];
            const float* hb = &h2[b * MODEL_DIM];
            #pragma unroll 8
            for (int i = 0; i < MODEL_DIM; i++)
                acc = fmaf(hb[i], tc_w2[i * MODEL_DIM + o], acc);
            hs[tid] = (acc >= 0.0f) ? acc : 0.2f * acc;
        }
        __syncthreads();
        // layer3: outdim 256 -> 2048 outputs, 2 per thread
        #pragma unroll
        for (int r = 0; r < 2; r++) {
            int oo = tid + r * 1024;
            int b = oo >> 8, o = oo & 255;
            float acc = tc_b3[o];
            const float* hb = &hs[b * MODEL_DIM];
            #pragma unroll 8
            for (int i = 0; i < MODEL_DIM; i++)
                acc = fmaf(hb[i], tc_w3[i * 256 + o], acc);
            out_s[oo] = acc;
        }
        __syncthreads();

        if (tid < BATCH * N_TABLES) {
            int b = tid >> 4, n = tid & 15;
            float s = 0.0f;
            #pragma unroll
            for (int k = 0; k < 16; k++) s += out_s[b * 256 + n * 16 + k];
            s_scores[tid] = s * (1.0f / 16.0f);
        }
        __syncthreads();
        if (tid < BATCH) {
            float best = s_scores[tid * N_TABLES];
            int bi = 0;
            #pragma unroll
            for (int n = 1; n < N_TABLES; n++) {
                float v = s_scores[tid * N_TABLES + n];
                if (v > best) { best = v; bi = n; }   // first-max ties == argmax
            }
            g_values[tid] = best;
            s_idx[tid] = bi;
        }
        __syncthreads();

        // ------------- normalize selected tables: warp w handles batch w -------------
        const int wid = tid >> 5, lane = tid & 31;
        if (wid < BATCH) {
            const float* row = wavetables + s_idx[wid] * TABLE_SIZE;
            float m = -3.4e38f;
            #pragma unroll
            for (int i = 0; i < 16; i++)
                m = fmaxf(m, __ldg(&row[lane + i * 32]));
            #pragma unroll
            for (int off = 16; off > 0; off >>= 1)
                m = fmaxf(m, __shfl_xor_sync(0xFFFFFFFFu, m, off));
            float denom = m + 1e-8f;
            #pragma unroll
            for (int i = 0; i < 16; i++) {
                int j = lane + i * 32;
                g_table[wid][j] = __ldg(&row[j]) / denom;
            }
        }
        __syncthreads();
        asm volatile("griddepcontrol.launch_dependents;" ::: "memory");
        return;
    }

    // ---------------- blocks 1..8: per-batch env/freq MLP + frame outputs ----------
    const int b = blockIdx.x - 1;

    __shared__ float s_x[MODEL_DIM];
    __shared__ float s_part[8 * MODEL_DIM];
    __shared__ float s_h[MODEL_DIM];
    __shared__ float s_env[N_FRAMES];
    __shared__ float s_freq[N_FRAMES];
    __shared__ float s_C[N_FRAMES];

    if (tid < MODEL_DIM) s_x[tid] = x[b * MODEL_DIM + tid];
    __syncthreads();

    const int r = tid >> 7;        // 0..7 : k-slice
    const int o = tid & 127;       // output index

    #define MLP3(W1, B1, W2, B2, W3, B3, DST)                                   \
    {                                                                            \
        float p = 0.0f;                                                          \
        {                                                                        \
            const int k0 = r * 16;                                               \
            _Pragma("unroll")                                                    \
            for (int k = 0; k < 16; k++)                                         \
                p = fmaf(s_x[k0 + k], W1[(k0 + k) * MODEL_DIM + o], p);          \
            s_part[r * MODEL_DIM + o] = p;                                       \
        }                                                                        \
        __syncthreads();                                                         \
        if (tid < MODEL_DIM) {                                                   \
            float acc = B1[tid];                                                 \
            _Pragma("unroll")                                                    \
            for (int rr = 0; rr < 8; rr++) acc += s_part[rr * MODEL_DIM + tid];  \
            s_h[tid] = (acc >= 0.0f) ? acc : 0.2f * acc;                         \
        }                                                                        \
        __syncthreads();                                                         \
        p = 0.0f;                                                                \
        {                                                                        \
            const int k0 = r * 16;                                               \
            _Pragma("unroll")                                                    \
            for (int k = 0; k < 16; k++)                                         \
                p = fmaf(s_h[k0 + k], W2[(k0 + k) * MODEL_DIM + o], p);          \
            s_part[r * MODEL_DIM + o] = p;                                       \
        }                                                                        \
        __syncthreads();                                                         \
        if (tid < MODEL_DIM) {                                                   \
            float acc = B2[tid];                                                 \
            _Pragma("unroll")                                                    \
            for (int rr = 0; rr < 8; rr++) acc += s_part[rr * MODEL_DIM + tid];  \
            s_part[tid] = (acc >= 0.0f) ? acc : 0.2f * acc;  /* reuse row 0 */   \
        }                                                                        \
        __syncthreads();                                                         \
        if (tid < MODEL_DIM) s_h[tid] = s_part[tid];                             \
        __syncthreads();                                                         \
        p = 0.0f;                                                                \
        {                                                                        \
            const int k0 = r * 16;                                               \
            _Pragma("unroll")                                                    \
            for (int k = 0; k < 16; k++)                                         \
                p = fmaf(s_h[k0 + k], W3[(k0 + k) * N_FRAMES + o], p);           \
            s_part[r * MODEL_DIM + o] = p;                                       \
        }                                                                        \
        __syncthreads();                                                         \
        if (tid < N_FRAMES) {                                                    \
            float acc = B3[tid];                                                 \
            _Pragma("unroll")                                                    \
            for (int rr = 0; rr < 8; rr++) acc += s_part[rr * MODEL_DIM + tid];  \
            DST[tid] = acc * acc;  /* squared */                                 \
        }                                                                        \
        __syncthreads();                                                         \
    }

    MLP3(env_w1, env_b1, env_w2, env_b2, env_w3, env_b3, s_env)
    MLP3(fr_w1,  fr_b1,  fr_w2,  fr_b2,  fr_w3,  fr_b3,  s_freq)

    // -------- segment prefix: a[0]=128*f0 (clamp region), a[j]=128*(f_{j-1}+f_j) --------
    if (tid < N_FRAMES) {
        s_C[tid] = (tid == 0) ? 128.0f * s_freq[0]
                              : 128.0f * (s_freq[tid - 1] + s_freq[tid]);
    }
    __syncthreads();
    // Hillis-Steele inclusive scan over 128 floats
    #pragma unroll
    for (int off = 1; off < N_FRAMES; off <<= 1) {
        float v = 0.0f;
        if (tid < N_FRAMES && tid >= off) v = s_C[tid - off];
        __syncthreads();
        if (tid < N_FRAMES && tid >= off) s_C[tid] += v;
        __syncthreads();
    }

    // frame-level outputs only (1.5 KB/batch) — writer reconstructs per-sample
    if (tid < N_FRAMES) {
        g_freqf[b][tid] = s_freq[tid];
        g_envf[b][tid]  = s_env[tid];
        g_C[b][tid]     = s_C[tid];
    }
    __syncthreads();
    asm volatile("griddepcontrol.launch_dependents;" ::: "memory");
}

// ---------------------------------------------------------------------------
// Fused writer (PDL secondary): waits on prep's grid dependency, then
// reconstructs phase/env warp-uniformly (fp32 closed form), writes the
// 512-col Gaussian row, accumulates sampled[b][t].
// ---------------------------------------------------------------------------
__global__ void fused_writer(float* __restrict__ out_kernel,
                             float* __restrict__ out_sampled)
{
    asm volatile("griddepcontrol.wait;" ::: "memory");

    const int wg = (blockIdx.x * blockDim.x + threadIdx.x) >> 5;   // row id
    const int lane = threadIdx.x & 31;
    const int b = wg >> 15;
    const int t = wg & (N_SAMPLES - 1);

    // ---- warp-uniform fp32 closed-form phase + env ----
    float c, envv;
    if (t < 128) {
        const float f0 = __ldg(&g_freqf[b][0]);
        c = (float)(t + 1) * f0;
        envv = __ldg(&g_envf[b][0]);
    } else if (t >= 32640) {
        c = __ldg(&g_C[b][127]) + (float)(t - 32639) * __ldg(&g_freqf[b][127]);
        envv = __ldg(&g_envf[b][127]);
    } else {
        const int k = (t - 128) >> 8;
        const int n = (t - 128) & 255;
        const float A  = __ldg(&g_freqf[b][k]);
        const float Bf = __ldg(&g_freqf[b][k + 1]) - A;
        const float np1 = (float)(n + 1);
        c = __ldg(&g_C[b][k]) + np1 * A + Bf * (np1 * np1 * (1.0f / 512.0f));
        const float w = ((float)n + 0.5f) * (1.0f / 256.0f);
        const float E0 = __ldg(&g_envf[b][k]);
        envv = fmaf(w, __ldg(&g_envf[b][k + 1]) - E0, E0);
    }
    const float phi = fmodf(c, 1.0f);

    const float p100 = phi * INV_STD;
    const int   jc   = __float2int_rn(phi * 511.0f);
    const int   clo  = jc - 70;
    const int   chi  = jc + 70;

    const float C2 = -0.7213475204444817f;   // -0.5 * log2(e)
    const float KB =  5.3180608409839085f;   // log2(GAUSS_SCALE)

    float4* rowp = reinterpret_cast<float4*>(out_kernel) + ((long long)wg << 7);
    const float4* tab4 = reinterpret_cast<const float4*>(g_table[b]);
    float acc = 0.0f;

    #pragma unroll
    for (int i = 0; i < 4; i++) {
        const int cblk = i * 128;
        if (chi < cblk || clo > cblk + 127) {
            float4 z4 = make_float4(0.0f, 0.0f, 0.0f, 0.0f);
            __stcs(&rowp[i * 32 + lane], z4);
        } else {
            const int col0 = (i * 32 + lane) * 4;
            const float4 tv = __ldg(&tab4[i * 32 + lane]);
            const float* tp = &tv.x;
            float4 v;
            float* vp = &v.x;
            #pragma unroll
            for (int k = 0; k < 4; k++) {
                float z = fmaf((float)(col0 + k), INV_STD / 511.0f, -p100);
                float e = ex2_ftz(fmaf(z * z, C2, KB));   // GAUSS_SCALE folded in
                vp[k] = e;
                acc = fmaf(tp[k], e, acc);
            }
            __stcs(&rowp[i * 32 + lane], v);
        }
    }

    #pragma unroll
    for (int off = 16; off > 0; off >>= 1)
        acc += __shfl_down_sync(0xFFFFFFFFu, acc, off);

    if (lane == 0)
        out_sampled[wg] = acc * envv * g_values[b];   // scale already in acc
}

// ---------------------------------------------------------------------------
extern "C" void kernel_launch(void* const* d_in, const int* in_sizes, int n_in,
                              void* d_out, int out_size)
{
    const float* x          = (const float*)d_in[0];
    const float* wavetables = (const float*)d_in[1];
    const float* tc_w1 = (const float*)d_in[2];  const float* tc_b1 = (const float*)d_in[3];
    const float* tc_w2 = (const float*)d_in[4];  const float* tc_b2 = (const float*)d_in[5];
    const float* tc_w3 = (const float*)d_in[6];  const float* tc_b3 = (const float*)d_in[7];
    const float* env_w1 = (const float*)d_in[8];  const float* env_b1 = (const float*)d_in[9];
    const float* env_w2 = (const float*)d_in[10]; const float* env_b2 = (const float*)d_in[11];
    const float* env_w3 = (const float*)d_in[12]; const float* env_b3 = (const float*)d_in[13];
    const float* fr_w1 = (const float*)d_in[14]; const float* fr_b1 = (const float*)d_in[15];
    const float* fr_w2 = (const float*)d_in[16]; const float* fr_b2 = (const float*)d_in[17];
    const float* fr_w3 = (const float*)d_in[18]; const float* fr_b3 = (const float*)d_in[19];

    float* out = (float*)d_out;
    float* out_sampled = out;                        // (8, 1, 32768)
    float* out_kernel  = out + BATCH * N_SAMPLES;    // (8, 32768, 512)

    prep_kernel<<<9, 1024>>>(x, wavetables,
        tc_w1, tc_b1, tc_w2, tc_b2, tc_w3, tc_b3,
        env_w1, env_b1, env_w2, env_b2, env_w3, env_b3,
        fr_w1, fr_b1, fr_w2, fr_b2, fr_w3, fr_b3);

    // PDL: writer launches while prep drains; griddepcontrol.wait inside
    // guarantees prep's global stores are visible before use.
    cudaLaunchConfig_t cfg = {};
    cfg.gridDim  = dim3((BATCH * N_SAMPLES) / 8, 1, 1);   // 32768 blocks
    cfg.blockDim = dim3(256, 1, 1);
    cfg.dynamicSmemBytes = 0;
    cfg.stream = 0;
    cudaLaunchAttribute attrs[1];
    attrs[0].id = cudaLaunchAttributeProgrammaticStreamSerialization;
    attrs[0].val.programmaticStreamSerializationAllowed = 1;
    cfg.attrs = attrs;
    cfg.numAttrs = 1;
    cudaLaunchKernelEx(&cfg, fused_writer, out_kernel, out_sampled);
}